// round 4
// baseline (speedup 1.0000x reference)
#include <cuda_runtime.h>
#include <cstdint>
#include <cstddef>

#define SDIM 4096
#define DEPTH 2

#define BM 128
#define BN 128
#define BK 8
#define NK (SDIM / BK)     // 512 k-tiles
#define NTN (SDIM / BN)    // 32 n-tiles

// ---------------- scratch (allocation-free: __device__ globals) ----------------
__device__ float g_d[SDIM];                 // per-position additive vector
__device__ float g_rowsum[DEPTH][SDIM];     // only used if sgu_ln_b != 0 (it is 0)
__device__ float g_part[NTN][SDIM];         // per-n-tile partial of the cls dot

__device__ __forceinline__ float gelu_exact(float x) {
    // jax.nn.gelu(approximate=False) = 0.5*x*(1+erf(x/sqrt(2)))
    return 0.5f * x * (1.0f + erff(x * 0.70710678118654752440f));
}

// ---------------------------------------------------------------------------
// Kernel 1: rowsum of sgu_proj_w[i][s][:], only needed if sgu_ln_b[i] != 0.
// For the actual dataset sgu_ln_b == 0, so every block early-exits (~few us).
// ---------------------------------------------------------------------------
__global__ void rowsum_kernel(const float* __restrict__ sgu_proj_w,
                              const float* __restrict__ sgu_ln_b) {
    int i = blockIdx.y;
    if (sgu_ln_b[i] == 0.0f) return;
    int s = blockIdx.x;
    const float* row = sgu_proj_w + ((size_t)i * SDIM + (size_t)s) * SDIM;
    float sum = 0.0f;
    for (int t = threadIdx.x; t < SDIM; t += blockDim.x) sum += row[t];
    __shared__ float sh[128];
    sh[threadIdx.x] = sum;
    __syncthreads();
    for (int o = 64; o > 0; o >>= 1) {
        if (threadIdx.x < o) sh[threadIdx.x] += sh[threadIdx.x + o];
        __syncthreads();
    }
    if (threadIdx.x == 0) g_rowsum[i][s] = sh[0];
}

// ---------------------------------------------------------------------------
// Kernel 2: d[s] = sum_i coef_i*(vc_i*rowsum_i[s] + sgu_proj_b[i,s]) + cp2_b[i]
// where coef_i = gelu(ln1_b[i]*cp1_w[i,0,0] + cp1_b[i,0]) * cp2_w[i,0,0]
// and vc_i = sgu_ln_b[i] (layernorm over a size-1 axis returns its bias).
// ---------------------------------------------------------------------------
__global__ void compute_d_kernel(const float* __restrict__ ln1_b,
                                 const float* __restrict__ cp1_w,
                                 const float* __restrict__ cp1_b,
                                 const float* __restrict__ sgu_ln_b,
                                 const float* __restrict__ sgu_proj_b,
                                 const float* __restrict__ cp2_w,
                                 const float* __restrict__ cp2_b) {
    int s = blockIdx.x * blockDim.x + threadIdx.x;
    if (s >= SDIM) return;
    float acc = 0.0f;
#pragma unroll
    for (int i = 0; i < DEPTH; i++) {
        // t = LN(h) over size-1 axis = ln1_b[i]
        float t = ln1_b[i];
        // u channel (column 0 of cp1): u = gelu(t*cp1_w[i,0,0] + cp1_b[i,0])
        float u = gelu_exact(t * cp1_w[i * 2 + 0] + cp1_b[i * 2 + 0]);
        float coef = u * cp2_w[i];     // cp2_w is (DEPTH,1,1)
        float vc = sgu_ln_b[i];        // LN(v) over size-1 axis = its bias
        float v = sgu_proj_b[i * SDIM + s];
        if (vc != 0.0f) v += vc * g_rowsum[i][s];
        acc += coef * v + cp2_b[i];
    }
    g_d[s] = acc;
}

// ---------------------------------------------------------------------------
// Kernel 3: GEMM  C[b,s] = sum_t (x[b,t]+d[t]) * pooler_w[s,t]
// fused epilogue: part[tile_n][b] = sum_{s in tile} gelu(C+pooler_b[s])*cls_w[s]
// 128x128x8 tiles, 256 threads, 8x8 microtile, double-buffered smem.
// ---------------------------------------------------------------------------
__global__ __launch_bounds__(256, 2)
void gemm_kernel(const float* __restrict__ X, const float* __restrict__ W,
                 const float* __restrict__ pooler_b,
                 const float* __restrict__ cls_w) {
    __shared__ float As[2][BK][BM + 4];
    __shared__ float Bs[2][BK][BN + 4];
    __shared__ float red[BM][17];

    const int tid = threadIdx.x;
    const int bm = blockIdx.y * BM;   // batch rows
    const int bn = blockIdx.x * BN;   // s columns

    // staging: 256 threads x float4 = 1024 floats = one 128x8 tile
    const int lr = tid >> 1;          // 0..127
    const int lc = (tid & 1) * 4;     // 0 or 4

    const float* Aptr = X + (size_t)(bm + lr) * SDIM + lc;
    const float* Bptr = W + (size_t)(bn + lr) * SDIM + lc;

    const int rm = (tid >> 4) * 8;    // microtile row base
    const int rn = (tid & 15) * 8;    // microtile col base

    float acc[8][8];
#pragma unroll
    for (int i = 0; i < 8; i++)
#pragma unroll
        for (int j = 0; j < 8; j++) acc[i][j] = 0.0f;

    // prologue: stage k-tile 0
    {
        float4 a4 = *(const float4*)(Aptr);
        float4 d4 = *(const float4*)(&g_d[lc]);
        float4 b4 = *(const float4*)(Bptr);
        As[0][lc + 0][lr] = a4.x + d4.x;
        As[0][lc + 1][lr] = a4.y + d4.y;
        As[0][lc + 2][lr] = a4.z + d4.z;
        As[0][lc + 3][lr] = a4.w + d4.w;
        Bs[0][lc + 0][lr] = b4.x;
        Bs[0][lc + 1][lr] = b4.y;
        Bs[0][lc + 2][lr] = b4.z;
        Bs[0][lc + 3][lr] = b4.w;
    }
    __syncthreads();

    int cur = 0;
    for (int kt = 0; kt < NK; kt++) {
        float4 na, nb, nd;
        if (kt < NK - 1) {
            const int k0 = (kt + 1) * BK;
            na = *(const float4*)(Aptr + k0);
            nd = *(const float4*)(&g_d[k0 + lc]);
            nb = *(const float4*)(Bptr + k0);
        }
#pragma unroll
        for (int k = 0; k < BK; k++) {
            float a[8], b[8];
#pragma unroll
            for (int i = 0; i < 8; i++) a[i] = As[cur][k][rm + i];
#pragma unroll
            for (int j = 0; j < 8; j++) b[j] = Bs[cur][k][rn + j];
#pragma unroll
            for (int i = 0; i < 8; i++)
#pragma unroll
                for (int j = 0; j < 8; j++)
                    acc[i][j] += a[i] * b[j];
        }
        if (kt < NK - 1) {
            const int nxt = cur ^ 1;
            As[nxt][lc + 0][lr] = na.x + nd.x;
            As[nxt][lc + 1][lr] = na.y + nd.y;
            As[nxt][lc + 2][lr] = na.z + nd.z;
            As[nxt][lc + 3][lr] = na.w + nd.w;
            Bs[nxt][lc + 0][lr] = nb.x;
            Bs[nxt][lc + 1][lr] = nb.y;
            Bs[nxt][lc + 2][lr] = nb.z;
            Bs[nxt][lc + 3][lr] = nb.w;
            __syncthreads();
            cur = nxt;
        }
    }

    // fused epilogue: gelu + dot with cls_w, reduce over this block's 128 s
    float rowacc[8];
#pragma unroll
    for (int i = 0; i < 8; i++) rowacc[i] = 0.0f;
#pragma unroll
    for (int j = 0; j < 8; j++) {
        const float pb = pooler_b[bn + rn + j];
        const float cw = cls_w[bn + rn + j];
#pragma unroll
        for (int i = 0; i < 8; i++)
            rowacc[i] += gelu_exact(acc[i][j] + pb) * cw;
    }
#pragma unroll
    for (int i = 0; i < 8; i++) red[rm + i][tid & 15] = rowacc[i];
    __syncthreads();
    if (tid < BM) {
        float s = 0.0f;
#pragma unroll
        for (int g = 0; g < 16; g++) s += red[tid][g];
        g_part[blockIdx.x][bm + tid] = s;   // deterministic: no atomics
    }
}

// ---------------------------------------------------------------------------
// Kernel 4: logits[b] = cls_b + sum over n-tiles of partials
// ---------------------------------------------------------------------------
__global__ void finalize_kernel(const float* __restrict__ cls_b,
                                float* __restrict__ out) {
    int b = blockIdx.x * blockDim.x + threadIdx.x;
    if (b >= SDIM) return;
    float s = cls_b[0];
#pragma unroll
    for (int t = 0; t < NTN; t++) s += g_part[t][b];
    out[b] = s;
}

// ---------------------------------------------------------------------------
extern "C" void kernel_launch(void* const* d_in, const int* in_sizes, int n_in,
                              void* d_out, int out_size) {
    const float* x          = (const float*)d_in[0];
    const float* ln1_b      = (const float*)d_in[2];
    const float* cp1_w      = (const float*)d_in[3];
    const float* cp1_b      = (const float*)d_in[4];
    const float* sgu_ln_b   = (const float*)d_in[6];
    const float* sgu_proj_w = (const float*)d_in[7];
    const float* sgu_proj_b = (const float*)d_in[8];
    const float* cp2_w      = (const float*)d_in[9];
    const float* cp2_b      = (const float*)d_in[10];
    const float* pooler_w   = (const float*)d_in[11];
    const float* pooler_b   = (const float*)d_in[12];
    const float* cls_w      = (const float*)d_in[13];
    const float* cls_b      = (const float*)d_in[14];
    float* out = (float*)d_out;

    (void)in_sizes; (void)n_in; (void)out_size;

    rowsum_kernel<<<dim3(SDIM, DEPTH), 128>>>(sgu_proj_w, sgu_ln_b);
    compute_d_kernel<<<SDIM / 256, 256>>>(ln1_b, cp1_w, cp1_b, sgu_ln_b,
                                          sgu_proj_b, cp2_w, cp2_b);
    gemm_kernel<<<dim3(SDIM / BN, SDIM / BM), 256>>>(x, pooler_w, pooler_b, cls_w);
    finalize_kernel<<<SDIM / 256, 256>>>(cls_b, out);
}

// round 11
// speedup vs baseline: 2.6872x; 2.6872x over previous
#include <cuda_runtime.h>
#include <cstdint>
#include <cstddef>

#define SDIM 4096
#define DEPTH 2

// GEMM tiling
#define BM 128
#define BN 128
#define BK 32
#define KITER (SDIM / BK)          // 128
#define ROWSTRIDE 36               // 32 floats + 4 pad: conflict-free frags & STS
#define ABUF (BM * ROWSTRIDE)      // 4608 floats per A buffer
#define BUFPAIR (2 * ABUF)         // A+B per stage
#define DSMEM (2 * BUFPAIR * 4)    // 73728 bytes
#define NTN (SDIM / BN)            // 32 n-tiles

// ---------------- scratch (allocation-free: __device__ globals) ----------------
__device__ __align__(16) float g_d[SDIM];
__device__ float g_rowsum[DEPTH][SDIM];
__device__ float g_part[NTN][SDIM];

__device__ __forceinline__ float gelu_exact(float x) {
    return 0.5f * x * (1.0f + erff(x * 0.70710678118654752440f));
}
__device__ __forceinline__ float tf32r(float v) {
    uint32_t u; asm("cvt.rna.tf32.f32 %0, %1;" : "=r"(u) : "f"(v));
    return __uint_as_float(u);
}
__device__ __forceinline__ void mma1688(float& c0, float& c1, float& c2, float& c3,
                                        uint32_t a0, uint32_t a1, uint32_t a2, uint32_t a3,
                                        uint32_t b0, uint32_t b1) {
    asm volatile(
        "mma.sync.aligned.m16n8k8.row.col.f32.tf32.tf32.f32 "
        "{%0,%1,%2,%3}, {%4,%5,%6,%7}, {%8,%9}, {%0,%1,%2,%3};"
        : "+f"(c0), "+f"(c1), "+f"(c2), "+f"(c3)
        : "r"(a0), "r"(a1), "r"(a2), "r"(a3), "r"(b0), "r"(b1));
}

// ---------------------------------------------------------------------------
// Kernel 1: rowsum of sgu_proj_w rows, only if sgu_ln_b != 0 (it is 0 -> ~free)
// ---------------------------------------------------------------------------
__global__ void rowsum_kernel(const float* __restrict__ sgu_proj_w,
                              const float* __restrict__ sgu_ln_b) {
    int i = blockIdx.y;
    if (sgu_ln_b[i] == 0.0f) return;
    int s = blockIdx.x;
    const float* row = sgu_proj_w + ((size_t)i * SDIM + (size_t)s) * SDIM;
    float sum = 0.0f;
    for (int t = threadIdx.x; t < SDIM; t += blockDim.x) sum += row[t];
    __shared__ float sh[128];
    sh[threadIdx.x] = sum;
    __syncthreads();
    for (int o = 64; o > 0; o >>= 1) {
        if (threadIdx.x < o) sh[threadIdx.x] += sh[threadIdx.x + o];
        __syncthreads();
    }
    if (threadIdx.x == 0) g_rowsum[i][s] = sh[0];
}

// ---------------------------------------------------------------------------
// Kernel 2: d[s] (collapsed transformer body: size-1 layernorms == their bias)
// ---------------------------------------------------------------------------
__global__ void compute_d_kernel(const float* __restrict__ ln1_b,
                                 const float* __restrict__ cp1_w,
                                 const float* __restrict__ cp1_b,
                                 const float* __restrict__ sgu_ln_b,
                                 const float* __restrict__ sgu_proj_b,
                                 const float* __restrict__ cp2_w,
                                 const float* __restrict__ cp2_b) {
    int s = blockIdx.x * blockDim.x + threadIdx.x;
    if (s >= SDIM) return;
    float acc = 0.0f;
#pragma unroll
    for (int i = 0; i < DEPTH; i++) {
        float t = ln1_b[i];
        float u = gelu_exact(t * cp1_w[i * 2 + 0] + cp1_b[i * 2 + 0]);
        float coef = u * cp2_w[i];
        float vc = sgu_ln_b[i];
        float v = sgu_proj_b[i * SDIM + s];
        if (vc != 0.0f) v += vc * g_rowsum[i][s];
        acc += coef * v + cp2_b[i];
    }
    g_d[s] = acc;
}

// ---------------------------------------------------------------------------
// Kernel 3: tf32 mma.sync GEMM  C[b,s] = sum_t tf32(x[b,t]+d[t]) * tf32(W[s,t])
// fused epilogue: gelu(C+pooler_b)*cls_w reduced over the CTA's 128 s-columns.
// 256 threads = 8 warps (2 M x 4 N), warp tile 64x32, double-buffered smem.
// ---------------------------------------------------------------------------
__global__ __launch_bounds__(256, 2)
void gemm_tc(const float* __restrict__ X, const float* __restrict__ W,
             const float* __restrict__ pooler_b, const float* __restrict__ cls_w) {
    extern __shared__ float smem[];   // [buf][A 4608 | B 4608]
    const int tid = threadIdx.x;
    const int lane = tid & 31;
    const int wid = tid >> 5;
    const int warpm = wid >> 2;       // 0..1
    const int warpn = wid & 3;        // 0..3
    const int g = lane >> 2;          // 0..7
    const int cq = lane & 3;          // 0..3

    const int bm = blockIdx.y * BM;
    const int bn = blockIdx.x * BN;

    // producer mapping: col4 = tid%8 (float4 column), rows m0+32i
    const int m0 = tid >> 3;          // 0..31
    const int col4 = tid & 7;         // 0..7
    const float* Ab = X + (size_t)(bm + m0) * SDIM + col4 * 4;
    const float* Bb = W + (size_t)(bn + m0) * SDIM + col4 * 4;

    float acc[4][4][4];
#pragma unroll
    for (int mt = 0; mt < 4; mt++)
#pragma unroll
        for (int nt = 0; nt < 4; nt++)
#pragma unroll
            for (int e = 0; e < 4; e++) acc[mt][nt][e] = 0.0f;

    // ---- stage k-chunk 0 ----
    {
        float* As = smem;
        float* Bs = smem + ABUF;
        float4 dv = *(const float4*)(g_d + col4 * 4);
#pragma unroll
        for (int i = 0; i < 4; i++) {
            float4 a = *(const float4*)(Ab + (size_t)(32 * i) * SDIM);
            float4 b = *(const float4*)(Bb + (size_t)(32 * i) * SDIM);
            float4 oa, ob;
            oa.x = tf32r(a.x + dv.x); oa.y = tf32r(a.y + dv.y);
            oa.z = tf32r(a.z + dv.z); oa.w = tf32r(a.w + dv.w);
            ob.x = tf32r(b.x); ob.y = tf32r(b.y);
            ob.z = tf32r(b.z); ob.w = tf32r(b.w);
            *(float4*)(As + (m0 + 32 * i) * ROWSTRIDE + col4 * 4) = oa;
            *(float4*)(Bs + (m0 + 32 * i) * ROWSTRIDE + col4 * 4) = ob;
        }
    }
    __syncthreads();

    int cur = 0;
    for (int kt = 0; kt < KITER; kt++) {
        // prefetch next chunk to regs
        float4 na[4], nb[4], nd;
        if (kt < KITER - 1) {
            const int k0 = (kt + 1) * BK;
            nd = *(const float4*)(g_d + k0 + col4 * 4);
#pragma unroll
            for (int i = 0; i < 4; i++) {
                na[i] = *(const float4*)(Ab + (size_t)(32 * i) * SDIM + k0);
                nb[i] = *(const float4*)(Bb + (size_t)(32 * i) * SDIM + k0);
            }
        }

        const uint32_t* As = (const uint32_t*)(smem + cur * BUFPAIR);
        const uint32_t* Bs = As + ABUF;
#pragma unroll
        for (int ks = 0; ks < 4; ks++) {
            const int kk = ks * 8 + cq;
            uint32_t af[4][4], bf[4][2];
#pragma unroll
            for (int mt = 0; mt < 4; mt++) {
                const int rm = (warpm * 64 + mt * 16 + g) * ROWSTRIDE + kk;
                af[mt][0] = As[rm];
                af[mt][1] = As[rm + 8 * ROWSTRIDE];
                af[mt][2] = As[rm + 4];
                af[mt][3] = As[rm + 8 * ROWSTRIDE + 4];
            }
#pragma unroll
            for (int nt = 0; nt < 4; nt++) {
                const int rn = (warpn * 32 + nt * 8 + g) * ROWSTRIDE + kk;
                bf[nt][0] = Bs[rn];
                bf[nt][1] = Bs[rn + 4];
            }
#pragma unroll
            for (int mt = 0; mt < 4; mt++)
#pragma unroll
                for (int nt = 0; nt < 4; nt++)
                    mma1688(acc[mt][nt][0], acc[mt][nt][1], acc[mt][nt][2], acc[mt][nt][3],
                            af[mt][0], af[mt][1], af[mt][2], af[mt][3],
                            bf[nt][0], bf[nt][1]);
        }

        if (kt < KITER - 1) {
            const int nxt = cur ^ 1;
            float* Asw = smem + nxt * BUFPAIR;
            float* Bsw = Asw + ABUF;
#pragma unroll
            for (int i = 0; i < 4; i++) {
                float4 oa, ob;
                oa.x = tf32r(na[i].x + nd.x); oa.y = tf32r(na[i].y + nd.y);
                oa.z = tf32r(na[i].z + nd.z); oa.w = tf32r(na[i].w + nd.w);
                ob.x = tf32r(nb[i].x); ob.y = tf32r(nb[i].y);
                ob.z = tf32r(nb[i].z); ob.w = tf32r(nb[i].w);
                *(float4*)(Asw + (m0 + 32 * i) * ROWSTRIDE + col4 * 4) = oa;
                *(float4*)(Bsw + (m0 + 32 * i) * ROWSTRIDE + col4 * 4) = ob;
            }
            __syncthreads();
            cur = nxt;
        }
    }

    // ---- fused epilogue: gelu + cls_w dot, deterministic per-n-tile partials ----
    // mma C layout: c0=(g, 2cq), c1=(g, 2cq+1), c2=(g+8, 2cq), c3=(g+8, 2cq+1)
    float rs[8];
#pragma unroll
    for (int i = 0; i < 8; i++) rs[i] = 0.0f;
#pragma unroll
    for (int nt = 0; nt < 4; nt++) {
        const int ncol = bn + warpn * 32 + nt * 8 + 2 * cq;
        const float pb0 = pooler_b[ncol], cw0 = cls_w[ncol];
        const float pb1 = pooler_b[ncol + 1], cw1 = cls_w[ncol + 1];
#pragma unroll
        for (int mt = 0; mt < 4; mt++) {
            rs[2 * mt + 0] += gelu_exact(acc[mt][nt][0] + pb0) * cw0
                            + gelu_exact(acc[mt][nt][1] + pb1) * cw1;
            rs[2 * mt + 1] += gelu_exact(acc[mt][nt][2] + pb0) * cw0
                            + gelu_exact(acc[mt][nt][3] + pb1) * cw1;
        }
    }
    // reduce across the 4 lanes sharing each row (lane%4 = quad)
#pragma unroll
    for (int off = 1; off <= 2; off <<= 1)
#pragma unroll
        for (int i = 0; i < 8; i++)
            rs[i] += __shfl_xor_sync(0xFFFFFFFF, rs[i], off);

    __syncthreads();                  // staging dead; reuse smem as reduction pad
    float* red = smem;                // [warpn][128 rows]
    if (cq == 0) {
#pragma unroll
        for (int mt = 0; mt < 4; mt++) {
#pragma unroll
            for (int h = 0; h < 2; h++) {
                const int row = warpm * 64 + mt * 16 + h * 8 + g;
                red[warpn * 128 + row] = rs[2 * mt + h];
            }
        }
    }
    __syncthreads();
    if (tid < BM) {
        float s = red[tid] + red[128 + tid] + red[256 + tid] + red[384 + tid];
        g_part[blockIdx.x][bm + tid] = s;
    }
}

// ---------------------------------------------------------------------------
// Kernel 4: logits[b] = cls_b + sum over n-tiles of partials
// ---------------------------------------------------------------------------
__global__ void finalize_kernel(const float* __restrict__ cls_b,
                                float* __restrict__ out) {
    int b = blockIdx.x * blockDim.x + threadIdx.x;
    if (b >= SDIM) return;
    float s = cls_b[0];
#pragma unroll
    for (int t = 0; t < NTN; t++) s += g_part[t][b];
    out[b] = s;
}

// ---------------------------------------------------------------------------
extern "C" void kernel_launch(void* const* d_in, const int* in_sizes, int n_in,
                              void* d_out, int out_size) {
    const float* x          = (const float*)d_in[0];
    const float* ln1_b      = (const float*)d_in[2];
    const float* cp1_w      = (const float*)d_in[3];
    const float* cp1_b      = (const float*)d_in[4];
    const float* sgu_ln_b   = (const float*)d_in[6];
    const float* sgu_proj_w = (const float*)d_in[7];
    const float* sgu_proj_b = (const float*)d_in[8];
    const float* cp2_w      = (const float*)d_in[9];
    const float* cp2_b      = (const float*)d_in[10];
    const float* pooler_w   = (const float*)d_in[11];
    const float* pooler_b   = (const float*)d_in[12];
    const float* cls_w      = (const float*)d_in[13];
    const float* cls_b      = (const float*)d_in[14];
    float* out = (float*)d_out;

    (void)in_sizes; (void)n_in; (void)out_size;

    cudaFuncSetAttribute(gemm_tc, cudaFuncAttributeMaxDynamicSharedMemorySize, DSMEM);

    rowsum_kernel<<<dim3(SDIM, DEPTH), 128>>>(sgu_proj_w, sgu_ln_b);
    compute_d_kernel<<<SDIM / 256, 256>>>(ln1_b, cp1_w, cp1_b, sgu_ln_b,
                                          sgu_proj_b, cp2_w, cp2_b);
    gemm_tc<<<dim3(SDIM / BN, SDIM / BM), 256, DSMEM>>>(x, pooler_w, pooler_b, cls_w);
    finalize_kernel<<<SDIM / 256, 256>>>(cls_b, out);
}

// round 12
// speedup vs baseline: 4.1909x; 1.5596x over previous
#include <cuda_runtime.h>
#include <cstdint>
#include <cstddef>

#define SDIM 4096
#define DEPTH 2

// GEMM tiling
#define BM 128
#define BN 128
#define BK 32
#define KITER (SDIM / BK)          // 128
#define ROWSTRIDE 36               // 32 floats + 4 pad: conflict-free STS/LDSM
#define ABUF (BM * ROWSTRIDE)      // 4608 floats per A (or B) buffer
#define BUFPAIR (2 * ABUF)         // A+B per stage
#define DSMEM (2 * BUFPAIR * 4)    // 73728 bytes
#define NTN (SDIM / BN)            // 32 n-tiles

// ---------------- scratch (allocation-free: __device__ globals) ----------------
__device__ __align__(16) float g_d[SDIM];
__device__ float g_rowsum[DEPTH][SDIM];
__device__ float g_part[NTN][SDIM];

__device__ __forceinline__ float gelu_exact(float x) {
    return 0.5f * x * (1.0f + erff(x * 0.70710678118654752440f));
}
__device__ __forceinline__ float tf32r(float v) {
    uint32_t u; asm("cvt.rna.tf32.f32 %0, %1;" : "=r"(u) : "f"(v));
    return __uint_as_float(u);
}
__device__ __forceinline__ uint32_t smem_u32(const void* p) {
    uint32_t a;
    asm("{ .reg .u64 t; cvta.to.shared.u64 t, %1; cvt.u32.u64 %0, t; }" : "=r"(a) : "l"(p));
    return a;
}
__device__ __forceinline__ void mma1688(float& c0, float& c1, float& c2, float& c3,
                                        uint32_t a0, uint32_t a1, uint32_t a2, uint32_t a3,
                                        uint32_t b0, uint32_t b1) {
    asm volatile(
        "mma.sync.aligned.m16n8k8.row.col.f32.tf32.tf32.f32 "
        "{%0,%1,%2,%3}, {%4,%5,%6,%7}, {%8,%9}, {%0,%1,%2,%3};"
        : "+f"(c0), "+f"(c1), "+f"(c2), "+f"(c3)
        : "r"(a0), "r"(a1), "r"(a2), "r"(a3), "r"(b0), "r"(b1));
}
__device__ __forceinline__ void ldsm4(uint32_t& r0, uint32_t& r1, uint32_t& r2,
                                      uint32_t& r3, uint32_t addr) {
    asm volatile("ldmatrix.sync.aligned.m8n8.x4.shared.b16 {%0,%1,%2,%3}, [%4];"
                 : "=r"(r0), "=r"(r1), "=r"(r2), "=r"(r3) : "r"(addr));
}
#define CP_ASYNC16(sa, gp) \
    asm volatile("cp.async.cg.shared.global [%0], [%1], 16;" :: "r"(sa), "l"(gp) : "memory")
#define CP_COMMIT() asm volatile("cp.async.commit_group;" ::: "memory")
#define CP_WAIT0()  asm volatile("cp.async.wait_group 0;" ::: "memory")

// ---------------------------------------------------------------------------
// Kernel 1: rowsum of sgu_proj_w rows, only if sgu_ln_b != 0 (it is 0 -> ~free)
// ---------------------------------------------------------------------------
__global__ void rowsum_kernel(const float* __restrict__ sgu_proj_w,
                              const float* __restrict__ sgu_ln_b) {
    int i = blockIdx.y;
    if (sgu_ln_b[i] == 0.0f) return;
    int s = blockIdx.x;
    const float* row = sgu_proj_w + ((size_t)i * SDIM + (size_t)s) * SDIM;
    float sum = 0.0f;
    for (int t = threadIdx.x; t < SDIM; t += blockDim.x) sum += row[t];
    __shared__ float sh[128];
    sh[threadIdx.x] = sum;
    __syncthreads();
    for (int o = 64; o > 0; o >>= 1) {
        if (threadIdx.x < o) sh[threadIdx.x] += sh[threadIdx.x + o];
        __syncthreads();
    }
    if (threadIdx.x == 0) g_rowsum[i][s] = sh[0];
}

// ---------------------------------------------------------------------------
// Kernel 2: d[s] (collapsed transformer body: size-1 layernorms == their bias)
// ---------------------------------------------------------------------------
__global__ void compute_d_kernel(const float* __restrict__ ln1_b,
                                 const float* __restrict__ cp1_w,
                                 const float* __restrict__ cp1_b,
                                 const float* __restrict__ sgu_ln_b,
                                 const float* __restrict__ sgu_proj_b,
                                 const float* __restrict__ cp2_w,
                                 const float* __restrict__ cp2_b) {
    int s = blockIdx.x * blockDim.x + threadIdx.x;
    if (s >= SDIM) return;
    float acc = 0.0f;
#pragma unroll
    for (int i = 0; i < DEPTH; i++) {
        float t = ln1_b[i];
        float u = gelu_exact(t * cp1_w[i * 2 + 0] + cp1_b[i * 2 + 0]);
        float coef = u * cp2_w[i];
        float vc = sgu_ln_b[i];
        float v = sgu_proj_b[i * SDIM + s];
        if (vc != 0.0f) v += vc * g_rowsum[i][s];
        acc += coef * v + cp2_b[i];
    }
    g_d[s] = acc;
}

// ---------------------------------------------------------------------------
// Kernel 3: tf32 mma.sync GEMM with ldmatrix fragment loads + cp.async B.
// C[b,s] = sum_t tf32(x[b,t]+d[t]) * tf32(W[s,t]); fused gelu+cls_w epilogue.
// 256 threads = 8 warps (2 M x 4 N), warp tile 64x32, double-buffered smem.
// ---------------------------------------------------------------------------
__global__ __launch_bounds__(256, 2)
void gemm_tc(const float* __restrict__ X, const float* __restrict__ W,
             const float* __restrict__ pooler_b, const float* __restrict__ cls_w) {
    extern __shared__ float smem[];   // [buf][A 4608 | B 4608] floats
    const uint32_t sdyn = smem_u32(smem);
    const int tid = threadIdx.x;
    const int lane = tid & 31;
    const int wid = tid >> 5;
    const int warpm = wid >> 2;       // 0..1
    const int warpn = wid & 3;        // 0..3
    const int g = lane >> 2;          // 0..7
    const int cq = lane & 3;          // 0..3

    const int bm = blockIdx.y * BM;
    const int bn = blockIdx.x * BN;

    // producer mapping: col4 = tid%8 (float4 column), rows m0+32i
    const int m0 = tid >> 3;          // 0..31
    const int col4 = tid & 7;         // 0..7
    const float* Ab = X + (size_t)(bm + m0) * SDIM + col4 * 4;
    const float* Bb = W + (size_t)(bn + m0) * SDIM + col4 * 4;

    // ldmatrix per-lane byte offsets (within a buffer)
    // A: lanes 0-7 rows 0-7 (m0->a0), 8-15 rows 8-15 (a1), 16-23 rows 0-7 col+4 (a2), 24-31 (a3)
    const uint32_t a_lane =
        (uint32_t)(((warpm * 64 + (lane & 15)) * ROWSTRIDE + ((lane >> 4) & 1) * 4) * 4);
    // B: m0=b0(nt even), m1=b1(even), m2=b0(odd), m3=b1(odd)
    const uint32_t b_lane =
        (uint32_t)(((warpn * 32 + ((lane >> 4) & 1) * 8 + (lane & 7)) * ROWSTRIDE
                    + ((lane >> 3) & 1) * 4) * 4 + ABUF * 4);

    float acc[4][4][4];
#pragma unroll
    for (int mt = 0; mt < 4; mt++)
#pragma unroll
        for (int nt = 0; nt < 4; nt++)
#pragma unroll
            for (int e = 0; e < 4; e++) acc[mt][nt][e] = 0.0f;

    // ---- prologue: stage k-chunk 0 (B via cp.async, A via regs with RNA + d) ----
    {
#pragma unroll
        for (int i = 0; i < 4; i++) {
            uint32_t dst = sdyn + (uint32_t)((ABUF + (m0 + 32 * i) * ROWSTRIDE + col4 * 4) * 4);
            CP_ASYNC16(dst, Bb + (size_t)(32 * i) * SDIM);
        }
        CP_COMMIT();
        float* As = smem;
        float4 dv = *(const float4*)(g_d + col4 * 4);
#pragma unroll
        for (int i = 0; i < 4; i++) {
            float4 a = *(const float4*)(Ab + (size_t)(32 * i) * SDIM);
            float4 oa;
            oa.x = tf32r(a.x + dv.x); oa.y = tf32r(a.y + dv.y);
            oa.z = tf32r(a.z + dv.z); oa.w = tf32r(a.w + dv.w);
            *(float4*)(As + (m0 + 32 * i) * ROWSTRIDE + col4 * 4) = oa;
        }
        CP_WAIT0();
    }
    __syncthreads();

    int cur = 0;
    for (int kt = 0; kt < KITER; kt++) {
        // prefetch next chunk: A to regs, B via cp.async into next buffer
        float4 na[4], nd;
        if (kt < KITER - 1) {
            const int k0 = (kt + 1) * BK;
            const int nxt = cur ^ 1;
#pragma unroll
            for (int i = 0; i < 4; i++) {
                uint32_t dst = sdyn + (uint32_t)((nxt * BUFPAIR + ABUF
                               + (m0 + 32 * i) * ROWSTRIDE + col4 * 4) * 4);
                CP_ASYNC16(dst, Bb + (size_t)(32 * i) * SDIM + k0);
            }
            CP_COMMIT();
            nd = *(const float4*)(g_d + k0 + col4 * 4);
#pragma unroll
            for (int i = 0; i < 4; i++)
                na[i] = *(const float4*)(Ab + (size_t)(32 * i) * SDIM + k0);
        }

        const uint32_t base = sdyn + (uint32_t)(cur * BUFPAIR * 4);
#pragma unroll
        for (int ks = 0; ks < 4; ks++) {
            uint32_t af[4][4], bf[4][2];
            const uint32_t ab = base + a_lane + ks * 32;
#pragma unroll
            for (int mt = 0; mt < 4; mt++)
                ldsm4(af[mt][0], af[mt][1], af[mt][2], af[mt][3],
                      ab + mt * (16 * ROWSTRIDE * 4));
            const uint32_t bb = base + b_lane + ks * 32;
            ldsm4(bf[0][0], bf[0][1], bf[1][0], bf[1][1], bb);
            ldsm4(bf[2][0], bf[2][1], bf[3][0], bf[3][1], bb + 16 * ROWSTRIDE * 4);
#pragma unroll
            for (int mt = 0; mt < 4; mt++)
#pragma unroll
                for (int nt = 0; nt < 4; nt++)
                    mma1688(acc[mt][nt][0], acc[mt][nt][1], acc[mt][nt][2], acc[mt][nt][3],
                            af[mt][0], af[mt][1], af[mt][2], af[mt][3],
                            bf[nt][0], bf[nt][1]);
        }

        if (kt < KITER - 1) {
            const int nxt = cur ^ 1;
            float* Asw = smem + nxt * BUFPAIR;
#pragma unroll
            for (int i = 0; i < 4; i++) {
                float4 oa;
                oa.x = tf32r(na[i].x + nd.x); oa.y = tf32r(na[i].y + nd.y);
                oa.z = tf32r(na[i].z + nd.z); oa.w = tf32r(na[i].w + nd.w);
                *(float4*)(Asw + (m0 + 32 * i) * ROWSTRIDE + col4 * 4) = oa;
            }
            CP_WAIT0();
            __syncthreads();
            cur = nxt;
        }
    }

    // ---- fused epilogue: gelu + cls_w dot, deterministic per-n-tile partials ----
    // mma C layout: c0=(g, 2cq), c1=(g, 2cq+1), c2=(g+8, 2cq), c3=(g+8, 2cq+1)
    float rs[8];
#pragma unroll
    for (int i = 0; i < 8; i++) rs[i] = 0.0f;
#pragma unroll
    for (int nt = 0; nt < 4; nt++) {
        const int ncol = bn + warpn * 32 + nt * 8 + 2 * cq;
        const float pb0 = pooler_b[ncol], cw0 = cls_w[ncol];
        const float pb1 = pooler_b[ncol + 1], cw1 = cls_w[ncol + 1];
#pragma unroll
        for (int mt = 0; mt < 4; mt++) {
            rs[2 * mt + 0] += gelu_exact(acc[mt][nt][0] + pb0) * cw0
                            + gelu_exact(acc[mt][nt][1] + pb1) * cw1;
            rs[2 * mt + 1] += gelu_exact(acc[mt][nt][2] + pb0) * cw0
                            + gelu_exact(acc[mt][nt][3] + pb1) * cw1;
        }
    }
#pragma unroll
    for (int off = 1; off <= 2; off <<= 1)
#pragma unroll
        for (int i = 0; i < 8; i++)
            rs[i] += __shfl_xor_sync(0xFFFFFFFF, rs[i], off);

    __syncthreads();                  // staging dead; reuse smem as reduction pad
    float* red = smem;                // [warpn][128 rows]
    if (cq == 0) {
#pragma unroll
        for (int mt = 0; mt < 4; mt++) {
#pragma unroll
            for (int h = 0; h < 2; h++) {
                const int row = warpm * 64 + mt * 16 + h * 8 + g;
                red[warpn * 128 + row] = rs[2 * mt + h];
            }
        }
    }
    __syncthreads();
    if (tid < BM) {
        float s = red[tid] + red[128 + tid] + red[256 + tid] + red[384 + tid];
        g_part[blockIdx.x][bm + tid] = s;
    }
}

// ---------------------------------------------------------------------------
// Kernel 4: logits[b] = cls_b + sum over n-tiles of partials
// ---------------------------------------------------------------------------
__global__ void finalize_kernel(const float* __restrict__ cls_b,
                                float* __restrict__ out) {
    int b = blockIdx.x * blockDim.x + threadIdx.x;
    if (b >= SDIM) return;
    float s = cls_b[0];
#pragma unroll
    for (int t = 0; t < NTN; t++) s += g_part[t][b];
    out[b] = s;
}

// ---------------------------------------------------------------------------
extern "C" void kernel_launch(void* const* d_in, const int* in_sizes, int n_in,
                              void* d_out, int out_size) {
    const float* x          = (const float*)d_in[0];
    const float* ln1_b      = (const float*)d_in[2];
    const float* cp1_w      = (const float*)d_in[3];
    const float* cp1_b      = (const float*)d_in[4];
    const float* sgu_ln_b   = (const float*)d_in[6];
    const float* sgu_proj_w = (const float*)d_in[7];
    const float* sgu_proj_b = (const float*)d_in[8];
    const float* cp2_w      = (const float*)d_in[9];
    const float* cp2_b      = (const float*)d_in[10];
    const float* pooler_w   = (const float*)d_in[11];
    const float* pooler_b   = (const float*)d_in[12];
    const float* cls_w      = (const float*)d_in[13];
    const float* cls_b      = (const float*)d_in[14];
    float* out = (float*)d_out;

    (void)in_sizes; (void)n_in; (void)out_size;

    cudaFuncSetAttribute(gemm_tc, cudaFuncAttributeMaxDynamicSharedMemorySize, DSMEM);

    rowsum_kernel<<<dim3(SDIM, DEPTH), 128>>>(sgu_proj_w, sgu_ln_b);
    compute_d_kernel<<<SDIM / 256, 256>>>(ln1_b, cp1_w, cp1_b, sgu_ln_b,
                                          sgu_proj_b, cp2_w, cp2_b);
    gemm_tc<<<dim3(SDIM / BN, SDIM / BM), 256, DSMEM>>>(x, pooler_w, pooler_b, cls_w);
    finalize_kernel<<<SDIM / 256, 256>>>(cls_b, out);
}